// round 4
// baseline (speedup 1.0000x reference)
#include <cuda_runtime.h>
#include <math.h>

#define D_MODEL 1024
#define NUM_HEADS 16
#define DK 64
#define SEQ 2048
#define BATCH 2
#define MROWS (BATCH * SEQ)  // 4096
#define LOG2EF 1.4426950408889634f
#define SBUF (128 * 24)

// Scratch buffers (device globals — no allocation allowed)
__device__ float g_Q[MROWS * D_MODEL];
__device__ float g_K[MROWS * D_MODEL];
__device__ float g_V[MROWS * D_MODEL];
__device__ float g_O[MROWS * D_MODEL];

__device__ __forceinline__ unsigned f2tf32(float v) {
    unsigned u;
    asm("cvt.rna.tf32.f32 %0, %1;" : "=r"(u) : "f"(v));
    return u;
}

#define MMA_TF32(D, A, B)                                                     \
    asm volatile(                                                             \
        "mma.sync.aligned.m16n8k8.row.col.f32.tf32.tf32.f32 "                 \
        "{%0,%1,%2,%3}, {%4,%5,%6,%7}, {%8,%9}, {%0,%1,%2,%3};\n"             \
        : "+f"((D)[0]), "+f"((D)[1]), "+f"((D)[2]), "+f"((D)[3])              \
        : "r"((A)[0]), "r"((A)[1]), "r"((A)[2]), "r"((A)[3]),                 \
          "r"((B).x), "r"((B).y))

// ---------------------------------------------------------------------------
// TF32 tensor-core GEMM body:  C = X[M][K] * W[N][K]^T  (NT)
// BM=BN=128, BK=16, 256 threads (8 warps, 2x4, warp tile 64x32).
// Double-buffered smem, ONE __syncthreads per k-iteration.
// ---------------------------------------------------------------------------
struct GemmRegs { float4 xa[2], xb[2]; };

__device__ __forceinline__ void g_load(const float* __restrict__ X,
                                       const float* __restrict__ W, int K,
                                       int m0, int n0, int k0, int tid,
                                       GemmRegs& R) {
#pragma unroll
    for (int it = 0; it < 2; it++) {
        int idx = tid + it * 256;
        int r = idx >> 2;
        int c = idx & 3;
        R.xa[it] = *(const float4*)&X[(size_t)(m0 + r) * K + k0 + 4 * c];
        R.xb[it] = *(const float4*)&W[(size_t)(n0 + r) * K + k0 + 4 * c];
    }
}

__device__ __forceinline__ void s_store(unsigned* __restrict__ As,
                                        unsigned* __restrict__ Bs, int tid,
                                        const GemmRegs& R) {
#pragma unroll
    for (int it = 0; it < 2; it++) {
        int idx = tid + it * 256;
        int r = idx >> 2;
        int c = idx & 3;
        int base = r * 24 + 8 * (c >> 1) + (c & 1);
        float va[4] = {R.xa[it].x, R.xa[it].y, R.xa[it].z, R.xa[it].w};
        float vb[4] = {R.xb[it].x, R.xb[it].y, R.xb[it].z, R.xb[it].w};
#pragma unroll
        for (int j = 0; j < 4; j++) {
            As[base + 2 * j] = f2tf32(va[j]);
            Bs[base + 2 * j] = f2tf32(vb[j]);
        }
    }
}

__device__ __forceinline__ void gemm_body(const float* __restrict__ X,
                                          const float* __restrict__ W,
                                          float* __restrict__ C,
                                          int M, int N, int K) {
    __shared__ unsigned As[2 * SBUF];
    __shared__ unsigned Bs[2 * SBUF];

    const int tid = threadIdx.x;
    const int lane = tid & 31;
    const int wid = tid >> 5;
    const int wr = wid >> 2;
    const int wc = wid & 3;
    const int m0 = blockIdx.y * 128;
    const int n0 = blockIdx.x * 128;
    const int g = lane >> 2;
    const int q = lane & 3;

    GemmRegs R;
    const int NIT = K >> 4;

    g_load(X, W, K, m0, n0, 0, tid, R);
    s_store(As, Bs, tid, R);
    g_load(X, W, K, m0, n0, 16, tid, R);
    __syncthreads();

    float acc[16][4] = {};

    for (int it = 0; it < NIT; it++) {
        const int cur = it & 1;
        if (it + 1 < NIT) s_store(As + (cur ^ 1) * SBUF, Bs + (cur ^ 1) * SBUF, tid, R);
        if (it + 2 < NIT) g_load(X, W, K, m0, n0, 16 * (it + 2), tid, R);

        const unsigned* Ac = As + cur * SBUF;
        const unsigned* Bc = Bs + cur * SBUF;
#pragma unroll
        for (int s = 0; s < 2; s++) {
            unsigned af[4][4];
            uint2 bf[4];
#pragma unroll
            for (int i = 0; i < 4; i++) {
                int arow = wr * 64 + i * 16 + g;
                uint2 lo = *(const uint2*)&Ac[arow * 24 + 8 * s + 2 * q];
                uint2 hi = *(const uint2*)&Ac[(arow + 8) * 24 + 8 * s + 2 * q];
                af[i][0] = lo.x; af[i][1] = hi.x; af[i][2] = lo.y; af[i][3] = hi.y;
            }
#pragma unroll
            for (int j = 0; j < 4; j++) {
                int brow = wc * 32 + j * 8 + g;
                bf[j] = *(const uint2*)&Bc[brow * 24 + 8 * s + 2 * q];
            }
#pragma unroll
            for (int i = 0; i < 4; i++) {
#pragma unroll
                for (int j = 0; j < 4; j++) {
                    MMA_TF32(acc[i * 4 + j], af[i], bf[j]);
                }
            }
        }
        __syncthreads();
    }

#pragma unroll
    for (int i = 0; i < 4; i++) {
        int row = m0 + wr * 64 + i * 16 + g;
#pragma unroll
        for (int j = 0; j < 4; j++) {
            int col = n0 + wc * 32 + j * 8 + 2 * q;
            float* d = acc[i * 4 + j];
            *(float2*)&C[(size_t)row * N + col] = make_float2(d[0], d[1]);
            *(float2*)&C[(size_t)(row + 8) * N + col] = make_float2(d[2], d[3]);
        }
    }
}

__global__ __launch_bounds__(256) void gemm_tf32(const float* __restrict__ X,
                                                 const float* __restrict__ W,
                                                 float* __restrict__ C,
                                                 int M, int N, int K) {
    gemm_body(X, W, C, M, N, K);
}

// Fused Q/K/V projection: blockIdx.z selects weight/output.
__global__ __launch_bounds__(256) void gemm_qkv(const float* __restrict__ X,
                                                const float* __restrict__ Wq,
                                                const float* __restrict__ Wk,
                                                const float* __restrict__ Wv,
                                                float* __restrict__ Cq,
                                                float* __restrict__ Ck,
                                                float* __restrict__ Cv) {
    const float* W = (blockIdx.z == 0) ? Wq : (blockIdx.z == 1) ? Wk : Wv;
    float* C = (blockIdx.z == 0) ? Cq : (blockIdx.z == 1) ? Ck : Cv;
    gemm_body(X, W, C, MROWS, D_MODEL, D_MODEL);
}

// ---------------------------------------------------------------------------
// RoPE in-place on Q and K.
// ---------------------------------------------------------------------------
__global__ __launch_bounds__(256) void rope_kernel(float* __restrict__ Q,
                                                   float* __restrict__ K,
                                                   const int* __restrict__ pos) {
    int idx = blockIdx.x * 256 + threadIdx.x;
    int row = idx >> 9;
    int pc = idx & 511;
    int p = pc & 31;
    int s = row & (SEQ - 1);

    float inv = expf((float)p * -0.28782313662425572f);
    float ang = (float)pos[s] * inv;
    float sv, cv;
    sincosf(ang, &sv, &cv);

    size_t off = (size_t)row * D_MODEL + 2 * pc;
    float2 qv = *(float2*)&Q[off];
    float2 kv = *(float2*)&K[off];
    *(float2*)&Q[off] = make_float2(qv.x * cv - qv.y * sv, qv.x * sv + qv.y * cv);
    *(float2*)&K[off] = make_float2(kv.x * cv - kv.y * sv, kv.x * sv + kv.y * cv);
}

// ---------------------------------------------------------------------------
// TF32 tensor-core causal flash attention (unchanged from round 3).
// ---------------------------------------------------------------------------
__global__ __launch_bounds__(256) void attn_tc(const float* __restrict__ Q,
                                               const float* __restrict__ K,
                                               const float* __restrict__ V,
                                               float* __restrict__ O) {
    extern __shared__ unsigned smem_u[];
    unsigned* Ks = smem_u;                 // 64 * 68
    unsigned* Vs = smem_u + 64 * 68;       // 64 * 68 (V transposed)
    unsigned* Psu = smem_u + 2 * 64 * 68;  // 128 * 68
    float* Psf = (float*)Psu;

    const int tid = threadIdx.x;
    const int lane = tid & 31;
    const int w = tid >> 5;
    const int g = lane >> 2;
    const int q = lane & 3;

    const int bh = blockIdx.y;
    const int b = bh >> 4;
    const int h = bh & 15;
    const int qt = (SEQ / 128 - 1) - blockIdx.x;
    const int q0 = qt * 128;

    const float* Qb = Q + (size_t)b * SEQ * D_MODEL + h * DK;
    const float* Kb = K + (size_t)b * SEQ * D_MODEL + h * DK;
    const float* Vb = V + (size_t)b * SEQ * D_MODEL + h * DK;
    float* Ob = O + (size_t)b * SEQ * D_MODEL + h * DK;

#pragma unroll
    for (int it = 0; it < 8; it++) {
        int idx = tid + it * 256;
        int r = idx >> 4;
        int c = (idx & 15) << 2;
        float4 v = *(const float4*)&Qb[(size_t)(q0 + r) * D_MODEL + c];
        *(float4*)&Psf[r * 68 + c] = v;
    }
    __syncthreads();

    unsigned qf[8][4];
    {
        int r0 = (16 * w + g) * 68;
        int r1 = (16 * w + g + 8) * 68;
#pragma unroll
        for (int s = 0; s < 8; s++) {
            qf[s][0] = f2tf32(Psf[r0 + 8 * s + q] * 0.125f);
            qf[s][1] = f2tf32(Psf[r1 + 8 * s + q] * 0.125f);
            qf[s][2] = f2tf32(Psf[r0 + 8 * s + q + 4] * 0.125f);
            qf[s][3] = f2tf32(Psf[r1 + 8 * s + q + 4] * 0.125f);
        }
    }

    float oacc[8][4] = {};
    float m0 = -1e30f, m1 = -1e30f, l0 = 0.f, l1 = 0.f;

    const int pr0 = (16 * w + g) * 68;
    const int pr1 = pr0 + 8 * 68;
    const int l0a = 2 * q;
    const int l1a = 2 * q + 1;
    const int pa = 2 * (l0a & 3) + (l0a >> 2);
    const int pb = 2 * (l1a & 3) + (l1a >> 2);

    const int nkt = (q0 + 128) >> 6;
    for (int kt = 0; kt < nkt; kt++) {
        const int k0 = kt << 6;
        __syncthreads();

#pragma unroll
        for (int it = 0; it < 4; it++) {
            int idx = tid + it * 256;
            int r = idx >> 4;
            int c = (idx & 15) << 2;
            float4 kv = *(const float4*)&Kb[(size_t)(k0 + r) * D_MODEL + c];
            float e[4] = {kv.x, kv.y, kv.z, kv.w};
#pragma unroll
            for (int j = 0; j < 4; j++) {
                int L = c + j;
                int pos = (L >> 3) * 8 + 2 * (L & 3) + ((L & 7) >> 2);
                Ks[r * 68 + pos] = f2tf32(e[j]);
            }
        }
#pragma unroll
        for (int it = 0; it < 4; it++) {
            int idx = tid + it * 256;
            int key = idx & 63;
            int c4 = idx >> 6;
            float4 vv = *(const float4*)&Vb[(size_t)(k0 + key) * D_MODEL + 4 * c4];
            int pk = (key >> 3) * 8 + 2 * (key & 3) + ((key & 7) >> 2);
            float e[4] = {vv.x, vv.y, vv.z, vv.w};
#pragma unroll
            for (int j = 0; j < 4; j++)
                Vs[(4 * c4 + j) * 68 + pk] = f2tf32(e[j]);
        }
        __syncthreads();

        float sacc[8][4];
#pragma unroll
        for (int j = 0; j < 8; j++)
#pragma unroll
            for (int r = 0; r < 4; r++) sacc[j][r] = 0.f;
#pragma unroll
        for (int j = 0; j < 8; j++) {
            int krow = (j * 8 + g) * 68;
#pragma unroll
            for (int s = 0; s < 8; s++) {
                uint2 bb = *(const uint2*)&Ks[krow + 8 * s + 2 * q];
                MMA_TF32(sacc[j], qf[s], bb);
            }
        }

        if (k0 + 63 > q0 + 16 * w) {
            int row0 = q0 + 16 * w + g;
            int row1 = row0 + 8;
#pragma unroll
            for (int j = 0; j < 8; j++) {
                int c0 = k0 + 8 * j + 2 * q;
                int c1 = c0 + 1;
                if (c0 > row0) sacc[j][0] = -1e30f;
                if (c1 > row0) sacc[j][1] = -1e30f;
                if (c0 > row1) sacc[j][2] = -1e30f;
                if (c1 > row1) sacc[j][3] = -1e30f;
            }
        }

        float mx0 = -1e30f, mx1 = -1e30f;
#pragma unroll
        for (int j = 0; j < 8; j++) {
            mx0 = fmaxf(mx0, fmaxf(sacc[j][0], sacc[j][1]));
            mx1 = fmaxf(mx1, fmaxf(sacc[j][2], sacc[j][3]));
        }
        mx0 = fmaxf(mx0, __shfl_xor_sync(0xffffffffu, mx0, 1));
        mx0 = fmaxf(mx0, __shfl_xor_sync(0xffffffffu, mx0, 2));
        mx1 = fmaxf(mx1, __shfl_xor_sync(0xffffffffu, mx1, 1));
        mx1 = fmaxf(mx1, __shfl_xor_sync(0xffffffffu, mx1, 2));

        float mn0 = fmaxf(m0, mx0);
        float mn1 = fmaxf(m1, mx1);
        float rs0 = exp2f((m0 - mn0) * LOG2EF);
        float rs1 = exp2f((m1 - mn1) * LOG2EF);
        m0 = mn0; m1 = mn1;

        float s0 = 0.f, s1 = 0.f;
#pragma unroll
        for (int j = 0; j < 8; j++) {
            float p0 = exp2f((sacc[j][0] - mn0) * LOG2EF);
            float p1 = exp2f((sacc[j][1] - mn0) * LOG2EF);
            float p2 = exp2f((sacc[j][2] - mn1) * LOG2EF);
            float p3 = exp2f((sacc[j][3] - mn1) * LOG2EF);
            s0 += p0 + p1;
            s1 += p2 + p3;
            Psu[pr0 + 8 * j + pa] = f2tf32(p0);
            Psu[pr0 + 8 * j + pb] = f2tf32(p1);
            Psu[pr1 + 8 * j + pa] = f2tf32(p2);
            Psu[pr1 + 8 * j + pb] = f2tf32(p3);
        }
        s0 += __shfl_xor_sync(0xffffffffu, s0, 1);
        s0 += __shfl_xor_sync(0xffffffffu, s0, 2);
        s1 += __shfl_xor_sync(0xffffffffu, s1, 1);
        s1 += __shfl_xor_sync(0xffffffffu, s1, 2);
        l0 = l0 * rs0 + s0;
        l1 = l1 * rs1 + s1;

#pragma unroll
        for (int j = 0; j < 8; j++) {
            oacc[j][0] *= rs0; oacc[j][1] *= rs0;
            oacc[j][2] *= rs1; oacc[j][3] *= rs1;
        }
        __syncwarp();

#pragma unroll
        for (int s = 0; s < 8; s++) {
            uint2 alo = *(const uint2*)&Psu[pr0 + 8 * s + 2 * q];
            uint2 ahi = *(const uint2*)&Psu[pr1 + 8 * s + 2 * q];
            unsigned af[4] = {alo.x, ahi.x, alo.y, ahi.y};
#pragma unroll
            for (int j = 0; j < 8; j++) {
                uint2 bb = *(const uint2*)&Vs[(j * 8 + g) * 68 + 8 * s + 2 * q];
                MMA_TF32(oacc[j], af, bb);
            }
        }
    }

    float inv0 = 1.f / l0;
    float inv1 = 1.f / l1;
    int row0 = q0 + 16 * w + g;
#pragma unroll
    for (int j = 0; j < 8; j++) {
        int col = 8 * j + 2 * q;
        *(float2*)&Ob[(size_t)row0 * D_MODEL + col] =
            make_float2(oacc[j][0] * inv0, oacc[j][1] * inv0);
        *(float2*)&Ob[(size_t)(row0 + 8) * D_MODEL + col] =
            make_float2(oacc[j][2] * inv1, oacc[j][3] * inv1);
    }
}

// ---------------------------------------------------------------------------
extern "C" void kernel_launch(void* const* d_in, const int* in_sizes, int n_in,
                              void* d_out, int out_size) {
    const float* x  = (const float*)d_in[0];
    const int*   ps = (const int*)d_in[1];
    const float* Wq = (const float*)d_in[2];
    const float* Wk = (const float*)d_in[3];
    const float* Wv = (const float*)d_in[4];
    const float* Wo = (const float*)d_in[5];
    float* out = (float*)d_out;

    float *gq, *gk, *gv, *go;
    cudaGetSymbolAddress((void**)&gq, g_Q);
    cudaGetSymbolAddress((void**)&gk, g_K);
    cudaGetSymbolAddress((void**)&gv, g_V);
    cudaGetSymbolAddress((void**)&go, g_O);

    const int attn_smem = 68 * 256 * 4;  // 69632 bytes
    cudaFuncSetAttribute(attn_tc, cudaFuncAttributeMaxDynamicSharedMemorySize,
                         attn_smem);

    gemm_qkv<<<dim3(8, 32, 3), 256>>>(x, Wq, Wk, Wv, gq, gk, gv);

    rope_kernel<<<(MROWS * 512) / 256, 256>>>(gq, gk, ps);

    attn_tc<<<dim3(SEQ / 128, BATCH * NUM_HEADS), 256, attn_smem>>>(gq, gk, gv, go);

    gemm_tf32<<<dim3(8, 32), 256>>>(go, Wo, out, MROWS, D_MODEL, D_MODEL);
}

// round 6
// speedup vs baseline: 1.0630x; 1.0630x over previous
#include <cuda_runtime.h>
#include <math.h>

#define D_MODEL 1024
#define NUM_HEADS 16
#define DK 64
#define SEQ 2048
#define BATCH 2
#define MROWS (BATCH * SEQ)  // 4096
#define LOG2EF 1.4426950408889634f

// Scratch buffers (device globals — no allocation allowed)
__device__ float g_Q[MROWS * D_MODEL];
__device__ float g_K[MROWS * D_MODEL];
__device__ float g_V[MROWS * D_MODEL];
__device__ float g_O[MROWS * D_MODEL];

__device__ __forceinline__ unsigned f2tf32(float v) {
    unsigned u;
    asm("cvt.rna.tf32.f32 %0, %1;" : "=r"(u) : "f"(v));
    return u;
}

#define MMA_TF32(D, A, B)                                                     \
    asm volatile(                                                             \
        "mma.sync.aligned.m16n8k8.row.col.f32.tf32.tf32.f32 "                 \
        "{%0,%1,%2,%3}, {%4,%5,%6,%7}, {%8,%9}, {%0,%1,%2,%3};\n"             \
        : "+f"((D)[0]), "+f"((D)[1]), "+f"((D)[2]), "+f"((D)[3])              \
        : "r"((A)[0]), "r"((A)[1]), "r"((A)[2]), "r"((A)[3]),                 \
          "r"((B).x), "r"((B).y))

// ---------------------------------------------------------------------------
// TF32 tensor-core GEMM:  C[M][N] = X[M][K] * W[N][K]^T   (NT)
// BM=128, BN=128, BK=16. 256 threads = 8 warps in 2x4 grid, warp tile 64x32.
// Single-buffered (R3 proven version).
// ---------------------------------------------------------------------------
__global__ __launch_bounds__(256) void gemm_tf32(const float* __restrict__ X,
                                                 const float* __restrict__ W,
                                                 float* __restrict__ C,
                                                 int M, int N, int K) {
    __shared__ unsigned As[128 * 24];
    __shared__ unsigned Bs[128 * 24];

    const int tid = threadIdx.x;
    const int lane = tid & 31;
    const int wid = tid >> 5;
    const int wr = wid >> 2;
    const int wc = wid & 3;
    const int m0 = blockIdx.y * 128;
    const int n0 = blockIdx.x * 128;

    const int g = lane >> 2;
    const int q = lane & 3;

    float4 xa[2], xb[2];

    auto load_g = [&](int k0) {
#pragma unroll
        for (int it = 0; it < 2; it++) {
            int idx = tid + it * 256;
            int r = idx >> 2;
            int c = idx & 3;
            xa[it] = *(const float4*)&X[(size_t)(m0 + r) * K + k0 + 4 * c];
            xb[it] = *(const float4*)&W[(size_t)(n0 + r) * K + k0 + 4 * c];
        }
    };
    auto store_s = [&]() {
#pragma unroll
        for (int it = 0; it < 2; it++) {
            int idx = tid + it * 256;
            int r = idx >> 2;
            int c = idx & 3;
            int base = r * 24 + 8 * (c >> 1) + (c & 1);
            float va[4] = {xa[it].x, xa[it].y, xa[it].z, xa[it].w};
            float vb[4] = {xb[it].x, xb[it].y, xb[it].z, xb[it].w};
#pragma unroll
            for (int j = 0; j < 4; j++) {
                As[base + 2 * j] = f2tf32(va[j]);
                Bs[base + 2 * j] = f2tf32(vb[j]);
            }
        }
    };

    float acc[16][4] = {};

    load_g(0);
    store_s();
    __syncthreads();

    for (int k0 = 16;; k0 += 16) {
        const bool last = (k0 >= K);
        if (!last) load_g(k0);

#pragma unroll
        for (int s = 0; s < 2; s++) {
            unsigned af[4][4];
            uint2 bf[4];
#pragma unroll
            for (int i = 0; i < 4; i++) {
                int arow = wr * 64 + i * 16 + g;
                uint2 lo = *(const uint2*)&As[arow * 24 + 8 * s + 2 * q];
                uint2 hi = *(const uint2*)&As[(arow + 8) * 24 + 8 * s + 2 * q];
                af[i][0] = lo.x; af[i][1] = hi.x; af[i][2] = lo.y; af[i][3] = hi.y;
            }
#pragma unroll
            for (int j = 0; j < 4; j++) {
                int brow = wc * 32 + j * 8 + g;
                bf[j] = *(const uint2*)&Bs[brow * 24 + 8 * s + 2 * q];
            }
#pragma unroll
            for (int i = 0; i < 4; i++) {
#pragma unroll
                for (int j = 0; j < 4; j++) {
                    MMA_TF32(acc[i * 4 + j], af[i], bf[j]);
                }
            }
        }

        __syncthreads();
        if (last) break;
        store_s();
        __syncthreads();
    }

#pragma unroll
    for (int i = 0; i < 4; i++) {
        int row = m0 + wr * 64 + i * 16 + g;
#pragma unroll
        for (int j = 0; j < 4; j++) {
            int col = n0 + wc * 32 + j * 8 + 2 * q;
            float* d = acc[i * 4 + j];
            *(float2*)&C[(size_t)row * N + col] = make_float2(d[0], d[1]);
            *(float2*)&C[(size_t)(row + 8) * N + col] = make_float2(d[2], d[3]);
        }
    }
}

// ---------------------------------------------------------------------------
// RoPE in-place on Q and K.
// ---------------------------------------------------------------------------
__global__ __launch_bounds__(256) void rope_kernel(float* __restrict__ Q,
                                                   float* __restrict__ K,
                                                   const int* __restrict__ pos) {
    int idx = blockIdx.x * 256 + threadIdx.x;
    int row = idx >> 9;
    int pc = idx & 511;
    int p = pc & 31;
    int s = row & (SEQ - 1);

    float inv = expf((float)p * -0.28782313662425572f);
    float ang = (float)pos[s] * inv;
    float sv, cv;
    sincosf(ang, &sv, &cv);

    size_t off = (size_t)row * D_MODEL + 2 * pc;
    float2 qv = *(float2*)&Q[off];
    float2 kv = *(float2*)&K[off];
    *(float2*)&Q[off] = make_float2(qv.x * cv - qv.y * sv, qv.x * sv + qv.y * cv);
    *(float2*)&K[off] = make_float2(kv.x * cv - kv.y * sv, kv.x * sv + kv.y * cv);
}

// ---------------------------------------------------------------------------
// TF32 tensor-core causal flash attention, occupancy-tuned:
// 128 threads (4 warps), Bq=64 (warp owns 16 q-rows), Bk=64.
// 4 CTAs/SM -> 4 warps/SMSP of independent dependency chains.
// ---------------------------------------------------------------------------
__global__ __launch_bounds__(128, 4) void attn_tc(const float* __restrict__ Q,
                                                  const float* __restrict__ K,
                                                  const float* __restrict__ V,
                                                  float* __restrict__ O) {
    extern __shared__ unsigned smem_u[];
    unsigned* Ks = smem_u;                 // 64 * 68
    unsigned* Vs = smem_u + 64 * 68;       // 64 * 68 (V transposed)
    unsigned* Psu = smem_u + 2 * 64 * 68;  // 64 * 68 (P tf32 bits / Q staging)
    float* Psf = (float*)Psu;

    const int tid = threadIdx.x;
    const int lane = tid & 31;
    const int w = tid >> 5;        // 0..3
    const int g = lane >> 2;
    const int q = lane & 3;

    const int bh = blockIdx.y;
    const int b = bh >> 4;
    const int h = bh & 15;
    const int qt = (SEQ / 64 - 1) - blockIdx.x;  // heavy tiles first
    const int q0 = qt * 64;

    const float* Qb = Q + (size_t)b * SEQ * D_MODEL + h * DK;
    const float* Kb = K + (size_t)b * SEQ * D_MODEL + h * DK;
    const float* Vb = V + (size_t)b * SEQ * D_MODEL + h * DK;
    float* Ob = O + (size_t)b * SEQ * D_MODEL + h * DK;

    // Stage Q tile (64 x 64 fp32) into Ps area
#pragma unroll
    for (int it = 0; it < 8; it++) {
        int idx = tid + it * 128;
        int r = idx >> 4;
        int c = (idx & 15) << 2;
        float4 v = *(const float4*)&Qb[(size_t)(q0 + r) * D_MODEL + c];
        *(float4*)&Psf[r * 68 + c] = v;
    }
    __syncthreads();

    // Extract Q fragments (scale 1/8 folded in), keep in registers
    unsigned qf[8][4];
    {
        int r0 = (16 * w + g) * 68;
        int r1 = (16 * w + g + 8) * 68;
#pragma unroll
        for (int s = 0; s < 8; s++) {
            qf[s][0] = f2tf32(Psf[r0 + 8 * s + q] * 0.125f);
            qf[s][1] = f2tf32(Psf[r1 + 8 * s + q] * 0.125f);
            qf[s][2] = f2tf32(Psf[r0 + 8 * s + q + 4] * 0.125f);
            qf[s][3] = f2tf32(Psf[r1 + 8 * s + q + 4] * 0.125f);
        }
    }

    float oacc[8][4] = {};
    float m0 = -1e30f, m1 = -1e30f, l0 = 0.f, l1 = 0.f;

    const int pr0 = (16 * w + g) * 68;
    const int pr1 = pr0 + 8 * 68;
    const int l0a = 2 * q;
    const int l1a = 2 * q + 1;
    const int pa = 2 * (l0a & 3) + (l0a >> 2);
    const int pb = 2 * (l1a & 3) + (l1a >> 2);

    const int nkt = qt + 1;
    for (int kt = 0; kt < nkt; kt++) {
        const int k0 = kt << 6;
        __syncthreads();   // prev iteration's Ks/Vs reads done

        // K tile (coalesced rows, interleaved tf32 store)
#pragma unroll
        for (int it = 0; it < 8; it++) {
            int idx = tid + it * 128;
            int r = idx >> 4;
            int c = (idx & 15) << 2;
            float4 kv = *(const float4*)&Kb[(size_t)(k0 + r) * D_MODEL + c];
            float e[4] = {kv.x, kv.y, kv.z, kv.w};
#pragma unroll
            for (int j = 0; j < 4; j++) {
                int L = c + j;
                int pos = (L >> 3) * 8 + 2 * (L & 3) + ((L & 7) >> 2);
                Ks[r * 68 + pos] = f2tf32(e[j]);
            }
        }
        // V tile transposed: Vs[dk_col][key interleaved]
#pragma unroll
        for (int it = 0; it < 8; it++) {
            int idx = tid + it * 128;
            int key = idx & 63;
            int c4 = idx >> 6;
            float4 vv = *(const float4*)&Vb[(size_t)(k0 + key) * D_MODEL + 4 * c4];
            int pk = (key >> 3) * 8 + 2 * (key & 3) + ((key & 7) >> 2);
            float e[4] = {vv.x, vv.y, vv.z, vv.w};
#pragma unroll
            for (int j = 0; j < 4; j++)
                Vs[(4 * c4 + j) * 68 + pk] = f2tf32(e[j]);
        }
        __syncthreads();

        // S = Q K^T  (warp: m16 x n64 x k64)
        float sacc[8][4];
#pragma unroll
        for (int j = 0; j < 8; j++)
#pragma unroll
            for (int r = 0; r < 4; r++) sacc[j][r] = 0.f;
#pragma unroll
        for (int j = 0; j < 8; j++) {
            int krow = (j * 8 + g) * 68;
#pragma unroll
            for (int s = 0; s < 8; s++) {
                uint2 bb = *(const uint2*)&Ks[krow + 8 * s + 2 * q];
                MMA_TF32(sacc[j], qf[s], bb);
            }
        }

        // Causal mask (only the diagonal tile needs it)
        if (k0 + 63 > q0 + 16 * w) {
            int row0 = q0 + 16 * w + g;
            int row1 = row0 + 8;
#pragma unroll
            for (int j = 0; j < 8; j++) {
                int c0 = k0 + 8 * j + 2 * q;
                int c1 = c0 + 1;
                if (c0 > row0) sacc[j][0] = -1e30f;
                if (c1 > row0) sacc[j][1] = -1e30f;
                if (c0 > row1) sacc[j][2] = -1e30f;
                if (c1 > row1) sacc[j][3] = -1e30f;
            }
        }

        // Row max (quad shuffle reduce)
        float mx0 = -1e30f, mx1 = -1e30f;
#pragma unroll
        for (int j = 0; j < 8; j++) {
            mx0 = fmaxf(mx0, fmaxf(sacc[j][0], sacc[j][1]));
            mx1 = fmaxf(mx1, fmaxf(sacc[j][2], sacc[j][3]));
        }
        mx0 = fmaxf(mx0, __shfl_xor_sync(0xffffffffu, mx0, 1));
        mx0 = fmaxf(mx0, __shfl_xor_sync(0xffffffffu, mx0, 2));
        mx1 = fmaxf(mx1, __shfl_xor_sync(0xffffffffu, mx1, 1));
        mx1 = fmaxf(mx1, __shfl_xor_sync(0xffffffffu, mx1, 2));

        float mn0 = fmaxf(m0, mx0);
        float mn1 = fmaxf(m1, mx1);
        float rs0 = exp2f((m0 - mn0) * LOG2EF);
        float rs1 = exp2f((m1 - mn1) * LOG2EF);
        m0 = mn0; m1 = mn1;

        float s0 = 0.f, s1 = 0.f;
#pragma unroll
        for (int j = 0; j < 8; j++) {
            float p0 = exp2f((sacc[j][0] - mn0) * LOG2EF);
            float p1 = exp2f((sacc[j][1] - mn0) * LOG2EF);
            float p2 = exp2f((sacc[j][2] - mn1) * LOG2EF);
            float p3 = exp2f((sacc[j][3] - mn1) * LOG2EF);
            s0 += p0 + p1;
            s1 += p2 + p3;
            Psu[pr0 + 8 * j + pa] = f2tf32(p0);
            Psu[pr0 + 8 * j + pb] = f2tf32(p1);
            Psu[pr1 + 8 * j + pa] = f2tf32(p2);
            Psu[pr1 + 8 * j + pb] = f2tf32(p3);
        }
        s0 += __shfl_xor_sync(0xffffffffu, s0, 1);
        s0 += __shfl_xor_sync(0xffffffffu, s0, 2);
        s1 += __shfl_xor_sync(0xffffffffu, s1, 1);
        s1 += __shfl_xor_sync(0xffffffffu, s1, 2);
        l0 = l0 * rs0 + s0;
        l1 = l1 * rs1 + s1;

        // Rescale O accumulators
#pragma unroll
        for (int j = 0; j < 8; j++) {
            oacc[j][0] *= rs0; oacc[j][1] *= rs0;
            oacc[j][2] *= rs1; oacc[j][3] *= rs1;
        }
        __syncwarp();  // Ps rows are per-warp

        // O += P V   (warp: m16 x n64 x k64)
#pragma unroll
        for (int s = 0; s < 8; s++) {
            uint2 alo = *(const uint2*)&Psu[pr0 + 8 * s + 2 * q];
            uint2 ahi = *(const uint2*)&Psu[pr1 + 8 * s + 2 * q];
            unsigned af[4] = {alo.x, ahi.x, alo.y, ahi.y};
#pragma unroll
            for (int j = 0; j < 8; j++) {
                uint2 bb = *(const uint2*)&Vs[(j * 8 + g) * 68 + 8 * s + 2 * q];
                MMA_TF32(oacc[j], af, bb);
            }
        }
    }

    // Epilogue
    float inv0 = 1.f / l0;
    float inv1 = 1.f / l1;
    int row0 = q0 + 16 * w + g;
#pragma unroll
    for (int j = 0; j < 8; j++) {
        int col = 8 * j + 2 * q;
        *(float2*)&Ob[(size_t)row0 * D_MODEL + col] =
            make_float2(oacc[j][0] * inv0, oacc[j][1] * inv0);
        *(float2*)&Ob[(size_t)(row0 + 8) * D_MODEL + col] =
            make_float2(oacc[j][2] * inv1, oacc[j][3] * inv1);
    }
}

// ---------------------------------------------------------------------------
extern "C" void kernel_launch(void* const* d_in, const int* in_sizes, int n_in,
                              void* d_out, int out_size) {
    const float* x  = (const float*)d_in[0];
    const int*   ps = (const int*)d_in[1];
    const float* Wq = (const float*)d_in[2];
    const float* Wk = (const float*)d_in[3];
    const float* Wv = (const float*)d_in[4];
    const float* Wo = (const float*)d_in[5];
    float* out = (float*)d_out;

    float *gq, *gk, *gv, *go;
    cudaGetSymbolAddress((void**)&gq, g_Q);
    cudaGetSymbolAddress((void**)&gk, g_K);
    cudaGetSymbolAddress((void**)&gv, g_V);
    cudaGetSymbolAddress((void**)&go, g_O);

    const int attn_smem = 3 * 64 * 68 * 4;  // 52224 bytes
    cudaFuncSetAttribute(attn_tc, cudaFuncAttributeMaxDynamicSharedMemorySize,
                         attn_smem);

    dim3 gg(D_MODEL / 128, MROWS / 128);   // (8, 32)
    gemm_tf32<<<gg, 256>>>(x, Wq, gq, MROWS, D_MODEL, D_MODEL);
    gemm_tf32<<<gg, 256>>>(x, Wk, gk, MROWS, D_MODEL, D_MODEL);
    gemm_tf32<<<gg, 256>>>(x, Wv, gv, MROWS, D_MODEL, D_MODEL);

    rope_kernel<<<(MROWS * 512) / 256, 256>>>(gq, gk, ps);

    attn_tc<<<dim3(SEQ / 64, BATCH * NUM_HEADS), 128, attn_smem>>>(gq, gk, gv, go);

    gemm_tf32<<<gg, 256>>>(go, Wo, out, MROWS, D_MODEL, D_MODEL);
}

// round 7
// speedup vs baseline: 1.0696x; 1.0063x over previous
#include <cuda_runtime.h>
#include <math.h>

#define D_MODEL 1024
#define NUM_HEADS 16
#define DK 64
#define SEQ 2048
#define BATCH 2
#define MROWS (BATCH * SEQ)  // 4096
#define LOG2EF 1.4426950408889634f

// Scratch buffers (device globals — no allocation allowed)
__device__ float g_Q[MROWS * D_MODEL];
__device__ float g_K[MROWS * D_MODEL];
__device__ float g_V[MROWS * D_MODEL];
__device__ float g_O[MROWS * D_MODEL];

__device__ __forceinline__ unsigned f2tf32(float v) {
    unsigned u;
    asm("cvt.rna.tf32.f32 %0, %1;" : "=r"(u) : "f"(v));
    return u;
}

#define MMA_TF32(D, A, B)                                                     \
    asm volatile(                                                             \
        "mma.sync.aligned.m16n8k8.row.col.f32.tf32.tf32.f32 "                 \
        "{%0,%1,%2,%3}, {%4,%5,%6,%7}, {%8,%9}, {%0,%1,%2,%3};\n"             \
        : "+f"((D)[0]), "+f"((D)[1]), "+f"((D)[2]), "+f"((D)[3])              \
        : "r"((A)[0]), "r"((A)[1]), "r"((A)[2]), "r"((A)[3]),                 \
          "r"((B).x), "r"((B).y))

// ---------------------------------------------------------------------------
// TF32 tensor-core GEMM:  C[M][N] = X[M][K] * W[N][K]^T   (NT)
// BM=BN=128, BK=16. 128 threads = 4 warps in 2x2 grid, warp tile 64x64.
// Bigger warp tile -> 33% less fragment LDS traffic per mma (L1-bound fix).
// ---------------------------------------------------------------------------
__global__ __launch_bounds__(128) void gemm_tf32(const float* __restrict__ X,
                                                 const float* __restrict__ W,
                                                 float* __restrict__ C,
                                                 int M, int N, int K) {
    __shared__ unsigned As[128 * 24];
    __shared__ unsigned Bs[128 * 24];

    const int tid = threadIdx.x;
    const int lane = tid & 31;
    const int wid = tid >> 5;      // 0..3
    const int wr = wid >> 1;       // warp row 0..1 (64 rows)
    const int wc = wid & 1;        // warp col 0..1 (64 cols)
    const int m0 = blockIdx.y * 128;
    const int n0 = blockIdx.x * 128;

    const int g = lane >> 2;
    const int q = lane & 3;

    float4 xa[4], xb[4];

    auto load_g = [&](int k0) {
#pragma unroll
        for (int it = 0; it < 4; it++) {
            int idx = tid + it * 128;
            int r = idx >> 2;
            int c = idx & 3;
            xa[it] = *(const float4*)&X[(size_t)(m0 + r) * K + k0 + 4 * c];
            xb[it] = *(const float4*)&W[(size_t)(n0 + r) * K + k0 + 4 * c];
        }
    };
    auto store_s = [&]() {
#pragma unroll
        for (int it = 0; it < 4; it++) {
            int idx = tid + it * 128;
            int r = idx >> 2;
            int c = idx & 3;
            int base = r * 24 + 8 * (c >> 1) + (c & 1);
            float va[4] = {xa[it].x, xa[it].y, xa[it].z, xa[it].w};
            float vb[4] = {xb[it].x, xb[it].y, xb[it].z, xb[it].w};
#pragma unroll
            for (int j = 0; j < 4; j++) {
                As[base + 2 * j] = f2tf32(va[j]);
                Bs[base + 2 * j] = f2tf32(vb[j]);
            }
        }
    };

    float acc[32][4] = {};   // [i(m16) * 8 + j(n8)][4]

    load_g(0);
    store_s();
    load_g(16);
    __syncthreads();

    for (int k0 = 16;; k0 += 16) {
        const bool last = (k0 >= K);

#pragma unroll
        for (int s = 0; s < 2; s++) {
            unsigned af[4][4];
            uint2 bf[8];
#pragma unroll
            for (int i = 0; i < 4; i++) {
                int arow = wr * 64 + i * 16 + g;
                uint2 lo = *(const uint2*)&As[arow * 24 + 8 * s + 2 * q];
                uint2 hi = *(const uint2*)&As[(arow + 8) * 24 + 8 * s + 2 * q];
                af[i][0] = lo.x; af[i][1] = hi.x; af[i][2] = lo.y; af[i][3] = hi.y;
            }
#pragma unroll
            for (int j = 0; j < 8; j++) {
                int brow = wc * 64 + j * 8 + g;
                bf[j] = *(const uint2*)&Bs[brow * 24 + 8 * s + 2 * q];
            }
#pragma unroll
            for (int i = 0; i < 4; i++) {
#pragma unroll
                for (int j = 0; j < 8; j++) {
                    MMA_TF32(acc[i * 8 + j], af[i], bf[j]);
                }
            }
        }

        __syncthreads();
        if (last) break;
        store_s();
        if (k0 + 16 < K) load_g(k0 + 16);
        __syncthreads();
    }

#pragma unroll
    for (int i = 0; i < 4; i++) {
        int row = m0 + wr * 64 + i * 16 + g;
#pragma unroll
        for (int j = 0; j < 8; j++) {
            int col = n0 + wc * 64 + j * 8 + 2 * q;
            float* d = acc[i * 8 + j];
            *(float2*)&C[(size_t)row * N + col] = make_float2(d[0], d[1]);
            *(float2*)&C[(size_t)(row + 8) * N + col] = make_float2(d[2], d[3]);
        }
    }
}

// ---------------------------------------------------------------------------
// RoPE in-place on Q and K.
// ---------------------------------------------------------------------------
__global__ __launch_bounds__(256) void rope_kernel(float* __restrict__ Q,
                                                   float* __restrict__ K,
                                                   const int* __restrict__ pos) {
    int idx = blockIdx.x * 256 + threadIdx.x;
    int row = idx >> 9;
    int pc = idx & 511;
    int p = pc & 31;
    int s = row & (SEQ - 1);

    float inv = expf((float)p * -0.28782313662425572f);
    float ang = (float)pos[s] * inv;
    float sv, cv;
    sincosf(ang, &sv, &cv);

    size_t off = (size_t)row * D_MODEL + 2 * pc;
    float2 qv = *(float2*)&Q[off];
    float2 kv = *(float2*)&K[off];
    *(float2*)&Q[off] = make_float2(qv.x * cv - qv.y * sv, qv.x * sv + qv.y * cv);
    *(float2*)&K[off] = make_float2(kv.x * cv - kv.y * sv, kv.x * sv + kv.y * cv);
}

// ---------------------------------------------------------------------------
// TF32 tensor-core causal flash attention with register-staged K/V prefetch:
// the LDG for tile kt+1 is issued right after tile kt's smem store, so gmem
// latency overlaps the mma/softmax compute phase instead of the critical path.
// 128 threads (4 warps), Bq=64, Bk=64.
// ---------------------------------------------------------------------------
__global__ __launch_bounds__(128) void attn_tc(const float* __restrict__ Q,
                                               const float* __restrict__ K,
                                               const float* __restrict__ V,
                                               float* __restrict__ O) {
    extern __shared__ unsigned smem_u[];
    unsigned* Ks = smem_u;                 // 64 * 68
    unsigned* Vs = smem_u + 64 * 68;       // 64 * 68 (V transposed)
    unsigned* Psu = smem_u + 2 * 64 * 68;  // 64 * 68 (P tf32 bits / Q staging)
    float* Psf = (float*)Psu;

    const int tid = threadIdx.x;
    const int lane = tid & 31;
    const int w = tid >> 5;        // 0..3
    const int g = lane >> 2;
    const int q = lane & 3;

    const int bh = blockIdx.y;
    const int b = bh >> 4;
    const int h = bh & 15;
    const int qt = (SEQ / 64 - 1) - blockIdx.x;  // heavy tiles first
    const int q0 = qt * 64;

    const float* Qb = Q + (size_t)b * SEQ * D_MODEL + h * DK;
    const float* Kb = K + (size_t)b * SEQ * D_MODEL + h * DK;
    const float* Vb = V + (size_t)b * SEQ * D_MODEL + h * DK;
    float* Ob = O + (size_t)b * SEQ * D_MODEL + h * DK;

    // K/V register staging (8 float4 each)
    float4 kreg[8], vreg[8];
    auto load_kv = [&](int k0) {
#pragma unroll
        for (int it = 0; it < 8; it++) {
            int idx = tid + it * 128;
            int r = idx >> 4;
            int c = (idx & 15) << 2;
            kreg[it] = *(const float4*)&Kb[(size_t)(k0 + r) * D_MODEL + c];
        }
#pragma unroll
        for (int it = 0; it < 8; it++) {
            int idx = tid + it * 128;
            int key = idx & 63;
            int c4 = idx >> 6;
            vreg[it] = *(const float4*)&Vb[(size_t)(k0 + key) * D_MODEL + 4 * c4];
        }
    };
    auto store_kv = [&]() {
#pragma unroll
        for (int it = 0; it < 8; it++) {
            int idx = tid + it * 128;
            int r = idx >> 4;
            int c = (idx & 15) << 2;
            float e[4] = {kreg[it].x, kreg[it].y, kreg[it].z, kreg[it].w};
#pragma unroll
            for (int j = 0; j < 4; j++) {
                int L = c + j;
                int pos = (L >> 3) * 8 + 2 * (L & 3) + ((L & 7) >> 2);
                Ks[r * 68 + pos] = f2tf32(e[j]);
            }
        }
#pragma unroll
        for (int it = 0; it < 8; it++) {
            int idx = tid + it * 128;
            int key = idx & 63;
            int c4 = idx >> 6;
            int pk = (key >> 3) * 8 + 2 * (key & 3) + ((key & 7) >> 2);
            float e[4] = {vreg[it].x, vreg[it].y, vreg[it].z, vreg[it].w};
#pragma unroll
            for (int j = 0; j < 4; j++)
                Vs[(4 * c4 + j) * 68 + pk] = f2tf32(e[j]);
        }
    };

    // Prefetch tile 0 first (overlaps with Q staging below)
    load_kv(0);

    // Stage Q tile (64 x 64 fp32) into Ps area
#pragma unroll
    for (int it = 0; it < 8; it++) {
        int idx = tid + it * 128;
        int r = idx >> 4;
        int c = (idx & 15) << 2;
        float4 v = *(const float4*)&Qb[(size_t)(q0 + r) * D_MODEL + c];
        *(float4*)&Psf[r * 68 + c] = v;
    }
    __syncthreads();

    // Extract Q fragments (scale 1/8 folded in), keep in registers
    unsigned qf[8][4];
    {
        int r0 = (16 * w + g) * 68;
        int r1 = (16 * w + g + 8) * 68;
#pragma unroll
        for (int s = 0; s < 8; s++) {
            qf[s][0] = f2tf32(Psf[r0 + 8 * s + q] * 0.125f);
            qf[s][1] = f2tf32(Psf[r1 + 8 * s + q] * 0.125f);
            qf[s][2] = f2tf32(Psf[r0 + 8 * s + q + 4] * 0.125f);
            qf[s][3] = f2tf32(Psf[r1 + 8 * s + q + 4] * 0.125f);
        }
    }

    float oacc[8][4] = {};
    float m0 = -1e30f, m1 = -1e30f, l0 = 0.f, l1 = 0.f;

    const int pr0 = (16 * w + g) * 68;
    const int pr1 = pr0 + 8 * 68;
    const int l0a = 2 * q;
    const int l1a = 2 * q + 1;
    const int pa = 2 * (l0a & 3) + (l0a >> 2);
    const int pb = 2 * (l1a & 3) + (l1a >> 2);

    const int nkt = qt + 1;
    for (int kt = 0; kt < nkt; kt++) {
        __syncthreads();   // prev iteration's Ks/Vs reads done (also covers Q staging)
        store_kv();
        __syncthreads();
        if (kt + 1 < nkt) load_kv((kt + 1) << 6);  // overlaps with compute below

        const int k0 = kt << 6;

        // S = Q K^T  (warp: m16 x n64 x k64)
        float sacc[8][4];
#pragma unroll
        for (int j = 0; j < 8; j++)
#pragma unroll
            for (int r = 0; r < 4; r++) sacc[j][r] = 0.f;
#pragma unroll
        for (int j = 0; j < 8; j++) {
            int krow = (j * 8 + g) * 68;
#pragma unroll
            for (int s = 0; s < 8; s++) {
                uint2 bb = *(const uint2*)&Ks[krow + 8 * s + 2 * q];
                MMA_TF32(sacc[j], qf[s], bb);
            }
        }

        // Causal mask (only the diagonal tile needs it)
        if (k0 + 63 > q0 + 16 * w) {
            int row0 = q0 + 16 * w + g;
            int row1 = row0 + 8;
#pragma unroll
            for (int j = 0; j < 8; j++) {
                int c0 = k0 + 8 * j + 2 * q;
                int c1 = c0 + 1;
                if (c0 > row0) sacc[j][0] = -1e30f;
                if (c1 > row0) sacc[j][1] = -1e30f;
                if (c0 > row1) sacc[j][2] = -1e30f;
                if (c1 > row1) sacc[j][3] = -1e30f;
            }
        }

        // Row max (quad shuffle reduce)
        float mx0 = -1e30f, mx1 = -1e30f;
#pragma unroll
        for (int j = 0; j < 8; j++) {
            mx0 = fmaxf(mx0, fmaxf(sacc[j][0], sacc[j][1]));
            mx1 = fmaxf(mx1, fmaxf(sacc[j][2], sacc[j][3]));
        }
        mx0 = fmaxf(mx0, __shfl_xor_sync(0xffffffffu, mx0, 1));
        mx0 = fmaxf(mx0, __shfl_xor_sync(0xffffffffu, mx0, 2));
        mx1 = fmaxf(mx1, __shfl_xor_sync(0xffffffffu, mx1, 1));
        mx1 = fmaxf(mx1, __shfl_xor_sync(0xffffffffu, mx1, 2));

        float mn0 = fmaxf(m0, mx0);
        float mn1 = fmaxf(m1, mx1);
        float rs0 = exp2f((m0 - mn0) * LOG2EF);
        float rs1 = exp2f((m1 - mn1) * LOG2EF);
        m0 = mn0; m1 = mn1;

        float s0 = 0.f, s1 = 0.f;
#pragma unroll
        for (int j = 0; j < 8; j++) {
            float p0 = exp2f((sacc[j][0] - mn0) * LOG2EF);
            float p1 = exp2f((sacc[j][1] - mn0) * LOG2EF);
            float p2 = exp2f((sacc[j][2] - mn1) * LOG2EF);
            float p3 = exp2f((sacc[j][3] - mn1) * LOG2EF);
            s0 += p0 + p1;
            s1 += p2 + p3;
            Psu[pr0 + 8 * j + pa] = f2tf32(p0);
            Psu[pr0 + 8 * j + pb] = f2tf32(p1);
            Psu[pr1 + 8 * j + pa] = f2tf32(p2);
            Psu[pr1 + 8 * j + pb] = f2tf32(p3);
        }
        s0 += __shfl_xor_sync(0xffffffffu, s0, 1);
        s0 += __shfl_xor_sync(0xffffffffu, s0, 2);
        s1 += __shfl_xor_sync(0xffffffffu, s1, 1);
        s1 += __shfl_xor_sync(0xffffffffu, s1, 2);
        l0 = l0 * rs0 + s0;
        l1 = l1 * rs1 + s1;

        // Rescale O accumulators
#pragma unroll
        for (int j = 0; j < 8; j++) {
            oacc[j][0] *= rs0; oacc[j][1] *= rs0;
            oacc[j][2] *= rs1; oacc[j][3] *= rs1;
        }
        __syncwarp();  // Ps rows are per-warp

        // O += P V   (warp: m16 x n64 x k64)
#pragma unroll
        for (int s = 0; s < 8; s++) {
            uint2 alo = *(const uint2*)&Psu[pr0 + 8 * s + 2 * q];
            uint2 ahi = *(const uint2*)&Psu[pr1 + 8 * s + 2 * q];
            unsigned af[4] = {alo.x, ahi.x, alo.y, ahi.y};
#pragma unroll
            for (int j = 0; j < 8; j++) {
                uint2 bb = *(const uint2*)&Vs[(j * 8 + g) * 68 + 8 * s + 2 * q];
                MMA_TF32(oacc[j], af, bb);
            }
        }
    }

    // Epilogue
    float inv0 = 1.f / l0;
    float inv1 = 1.f / l1;
    int row0 = q0 + 16 * w + g;
#pragma unroll
    for (int j = 0; j < 8; j++) {
        int col = 8 * j + 2 * q;
        *(float2*)&Ob[(size_t)row0 * D_MODEL + col] =
            make_float2(oacc[j][0] * inv0, oacc[j][1] * inv0);
        *(float2*)&Ob[(size_t)(row0 + 8) * D_MODEL + col] =
            make_float2(oacc[j][2] * inv1, oacc[j][3] * inv1);
    }
}

// ---------------------------------------------------------------------------
extern "C" void kernel_launch(void* const* d_in, const int* in_sizes, int n_in,
                              void* d_out, int out_size) {
    const float* x  = (const float*)d_in[0];
    const int*   ps = (const int*)d_in[1];
    const float* Wq = (const float*)d_in[2];
    const float* Wk = (const float*)d_in[3];
    const float* Wv = (const float*)d_in[4];
    const float* Wo = (const float*)d_in[5];
    float* out = (float*)d_out;

    float *gq, *gk, *gv, *go;
    cudaGetSymbolAddress((void**)&gq, g_Q);
    cudaGetSymbolAddress((void**)&gk, g_K);
    cudaGetSymbolAddress((void**)&gv, g_V);
    cudaGetSymbolAddress((void**)&go, g_O);

    const int attn_smem = 3 * 64 * 68 * 4;  // 52224 bytes
    cudaFuncSetAttribute(attn_tc, cudaFuncAttributeMaxDynamicSharedMemorySize,
                         attn_smem);

    dim3 gg(D_MODEL / 128, MROWS / 128);   // (8, 32)
    gemm_tf32<<<gg, 128>>>(x, Wq, gq, MROWS, D_MODEL, D_MODEL);
    gemm_tf32<<<gg, 128>>>(x, Wk, gk, MROWS, D_MODEL, D_MODEL);
    gemm_tf32<<<gg, 128>>>(x, Wv, gv, MROWS, D_MODEL, D_MODEL);

    rope_kernel<<<(MROWS * 512) / 256, 256>>>(gq, gk, ps);

    attn_tc<<<dim3(SEQ / 64, BATCH * NUM_HEADS), 128, attn_smem>>>(gq, gk, gv, go);

    gemm_tf32<<<gg, 128>>>(go, Wo, out, MROWS, D_MODEL, D_MODEL);
}

// round 8
// speedup vs baseline: 1.3701x; 1.2809x over previous
#include <cuda_runtime.h>
#include <math.h>

#define D_MODEL 1024
#define NUM_HEADS 16
#define DK 64
#define SEQ 2048
#define BATCH 2
#define MROWS (BATCH * SEQ)  // 4096
#define LOG2EF 1.4426950408889634f

// ---------------------------------------------------------------------------
// Scratch buffers (device globals — no allocation allowed)
// fp32 intermediates
__device__ float g_Q[MROWS * D_MODEL];
__device__ float g_K[MROWS * D_MODEL];
__device__ float g_V[MROWS * D_MODEL];
// packed tf32-bit operands (fragment-permuted layout)
__device__ unsigned g_Xp[MROWS * D_MODEL];
__device__ unsigned g_Wqp[D_MODEL * D_MODEL];
__device__ unsigned g_Wkp[D_MODEL * D_MODEL];
__device__ unsigned g_Wvp[D_MODEL * D_MODEL];
__device__ unsigned g_Wop[D_MODEL * D_MODEL];
__device__ unsigned g_Qp[MROWS * D_MODEL];   // [bh][2048][64]
__device__ unsigned g_Kp[MROWS * D_MODEL];   // [bh][2048][64]
__device__ unsigned g_Vtp[MROWS * D_MODEL];  // [bh][32][64 dk][64 pkey]
__device__ unsigned g_Op[MROWS * D_MODEL];   // [row][1024] packed

__device__ __forceinline__ unsigned f2tf32(float v) {
    unsigned u;
    asm("cvt.rna.tf32.f32 %0, %1;" : "=r"(u) : "f"(v));
    return u;
}
__device__ __forceinline__ int perm8(int l) { return 2 * (l & 3) + (l >> 2); }
__device__ __forceinline__ int inv8(int p) { return 4 * (p & 1) + (p >> 1); }

__device__ __forceinline__ unsigned smem_u32p(const void* p) {
    unsigned a;
    asm("{ .reg .u64 t; cvta.to.shared.u64 t, %1; cvt.u32.u64 %0, t; }"
        : "=r"(a) : "l"(p));
    return a;
}
__device__ __forceinline__ void cp16(unsigned smem, const void* g) {
    asm volatile("cp.async.cg.shared.global [%0], [%1], 16;"
                 :: "r"(smem), "l"(g));
}
#define CP_COMMIT() asm volatile("cp.async.commit_group;" ::: "memory")
#define CP_WAIT(n) asm volatile("cp.async.wait_group %0;" :: "n"(n) : "memory")

#define MMA_TF32(D, A, B)                                                     \
    asm volatile(                                                             \
        "mma.sync.aligned.m16n8k8.row.col.f32.tf32.tf32.f32 "                 \
        "{%0,%1,%2,%3}, {%4,%5,%6,%7}, {%8,%9}, {%0,%1,%2,%3};\n"             \
        : "+f"((D)[0]), "+f"((D)[1]), "+f"((D)[2]), "+f"((D)[3])              \
        : "r"((A)[0]), "r"((A)[1]), "r"((A)[2]), "r"((A)[3]),                 \
          "r"((B).x), "r"((B).y))

// ---------------------------------------------------------------------------
// pack_rows: fp32 row-major -> tf32 bits in fragment order (perm8 per 8-block)
// dst[p] = tf32(src[inv8(p)]) within each 8-col block.
// ---------------------------------------------------------------------------
__global__ __launch_bounds__(256) void pack_rows(const float* __restrict__ src,
                                                 unsigned* __restrict__ dst,
                                                 int total8) {
    int i = blockIdx.x * 256 + threadIdx.x;
    if (i >= total8) return;
    const float* s = src + (size_t)i * 8;
    float4 a = *(const float4*)s;
    float4 b = *(const float4*)(s + 4);
    uint4 o0 = make_uint4(f2tf32(a.x), f2tf32(b.x), f2tf32(a.y), f2tf32(b.y));
    uint4 o1 = make_uint4(f2tf32(a.z), f2tf32(b.z), f2tf32(a.w), f2tf32(b.w));
    *(uint4*)(dst + (size_t)i * 8) = o0;
    *(uint4*)(dst + (size_t)i * 8 + 4) = o1;
}

// ---------------------------------------------------------------------------
// rope_pack: read fp32 Q/K, rotate, write packed tf32 Qp (x1/8) and Kp,
// head-major layout [bh][2048][64].
// ---------------------------------------------------------------------------
__global__ __launch_bounds__(256) void rope_pack(const float* __restrict__ Qf,
                                                 const float* __restrict__ Kf,
                                                 const int* __restrict__ pos,
                                                 unsigned* __restrict__ Qp,
                                                 unsigned* __restrict__ Kp) {
    int idx = blockIdx.x * 256 + threadIdx.x;
    int row = idx >> 9;          // b*2048 + s
    int pc = idx & 511;          // h*32 + p
    int h = pc >> 5;
    int p = pc & 31;
    int s = row & (SEQ - 1);
    int b = row >> 11;

    float inv = expf((float)p * -0.28782313662425572f);
    float ang = (float)pos[s] * inv;
    float sv, cv;
    sincosf(ang, &sv, &cv);

    size_t off = (size_t)row * D_MODEL + 2 * pc;
    float2 qv = *(const float2*)&Qf[off];
    float2 kv = *(const float2*)&Kf[off];
    float2 qo = make_float2(qv.x * cv - qv.y * sv, qv.x * sv + qv.y * cv);
    float2 ko = make_float2(kv.x * cv - kv.y * sv, kv.x * sv + kv.y * cv);

    int L = 2 * p;
    int ph0 = 8 * (L >> 3) + perm8(L & 7);
    int ph1 = 8 * (L >> 3) + perm8((L + 1) & 7);
    size_t dbase = ((size_t)(b * 16 + h) * SEQ + s) * 64;
    Qp[dbase + ph0] = f2tf32(qo.x * 0.125f);
    Qp[dbase + ph1] = f2tf32(qo.y * 0.125f);
    Kp[dbase + ph0] = f2tf32(ko.x);
    Kp[dbase + ph1] = f2tf32(ko.y);
}

// ---------------------------------------------------------------------------
// pack_vt: V fp32 [b,s,1024] -> Vtp [bh][t][dk 64][pkey 64] tf32 (transposed,
// key index fragment-permuted). Tiled smem transpose.
// ---------------------------------------------------------------------------
__global__ __launch_bounds__(256) void pack_vt(const float* __restrict__ V,
                                               unsigned* __restrict__ Vtp) {
    __shared__ float sm[64 * 65];
    const int t = blockIdx.x;    // 0..31
    const int bh = blockIdx.y;   // 0..31
    const int b = bh >> 4, h = bh & 15;
    const int tid = threadIdx.x;

    const float* src = V + ((size_t)(b * SEQ + t * 64)) * D_MODEL + h * 64;
#pragma unroll
    for (int it = 0; it < 4; it++) {
        int idx = tid + it * 256;
        int key = idx >> 4;
        int c4 = (idx & 15) << 2;
        float4 v = *(const float4*)&src[(size_t)key * D_MODEL + c4];
        sm[key * 65 + c4 + 0] = v.x;
        sm[key * 65 + c4 + 1] = v.y;
        sm[key * 65 + c4 + 2] = v.z;
        sm[key * 65 + c4 + 3] = v.w;
    }
    __syncthreads();
    unsigned* dst = Vtp + ((size_t)bh * 32 + t) * 4096;
#pragma unroll
    for (int it = 0; it < 16; it++) {
        int idx = tid + it * 256;
        int dk = idx >> 6;
        int p = idx & 63;
        int key = 8 * (p >> 3) + inv8(p & 7);
        dst[idx] = f2tf32(sm[key * 65 + dk]);
    }
}

// ---------------------------------------------------------------------------
// Packed tf32 GEMM: C[M][N] = A[M][1024] * B[N][1024]^T, A/B pre-packed.
// BM=BN=128, BK=16, 128 threads (4 warps, 2x2, warp tile 64x64).
// cp.async double-buffered fills; inner loop = LDS + MMA only.
// ---------------------------------------------------------------------------
#define GK 1024
#define GNIT 64
__device__ __forceinline__ void gemm_pk_body(const unsigned* __restrict__ A,
                                             const unsigned* __restrict__ B,
                                             float* __restrict__ C, int N) {
    extern __shared__ unsigned gsm[];
    // layout (u32): A0 [0,3072) B0 [3072,6144) A1 [6144,9216) B1 [9216,12288)
    const unsigned smb = smem_u32p(gsm);

    const int tid = threadIdx.x;
    const int lane = tid & 31;
    const int wid = tid >> 5;
    const int wr = wid >> 1;
    const int wc = wid & 1;
    const int m0 = blockIdx.y * 128;
    const int n0 = blockIdx.x * 128;
    const int g = lane >> 2;
    const int q = lane & 3;

    auto fill = [&](int buf, int k0) {
#pragma unroll
        for (int it = 0; it < 4; it++) {
            int idx = tid + it * 128;   // 0..511
            int r = idx >> 2;
            int c = idx & 3;
            cp16(smb + (buf * 6144 + r * 24 + 4 * c) * 4,
                 A + (size_t)(m0 + r) * GK + k0 + 4 * c);
        }
#pragma unroll
        for (int it = 0; it < 4; it++) {
            int idx = tid + it * 128;
            int r = idx >> 2;
            int c = idx & 3;
            cp16(smb + (3072 + buf * 6144 + r * 24 + 4 * c) * 4,
                 B + (size_t)(n0 + r) * GK + k0 + 4 * c);
        }
        CP_COMMIT();
    };

    fill(0, 0);
    fill(1, 16);

    float acc[32][4] = {};

    for (int it = 0; it < GNIT; it++) {
        const int cur = it & 1;
        if (it + 1 < GNIT) { CP_WAIT(1); } else { CP_WAIT(0); }
        __syncthreads();

        const unsigned* Ac = gsm + cur * 6144;
        const unsigned* Bc = gsm + 3072 + cur * 6144;
#pragma unroll
        for (int s = 0; s < 2; s++) {
            unsigned af[4][4];
            uint2 bf[8];
#pragma unroll
            for (int i = 0; i < 4; i++) {
                int arow = wr * 64 + i * 16 + g;
                uint2 lo = *(const uint2*)&Ac[arow * 24 + 8 * s + 2 * q];
                uint2 hi = *(const uint2*)&Ac[(arow + 8) * 24 + 8 * s + 2 * q];
                af[i][0] = lo.x; af[i][1] = hi.x; af[i][2] = lo.y; af[i][3] = hi.y;
            }
#pragma unroll
            for (int j = 0; j < 8; j++) {
                int brow = wc * 64 + j * 8 + g;
                bf[j] = *(const uint2*)&Bc[brow * 24 + 8 * s + 2 * q];
            }
#pragma unroll
            for (int i = 0; i < 4; i++) {
#pragma unroll
                for (int j = 0; j < 8; j++) {
                    MMA_TF32(acc[i * 8 + j], af[i], bf[j]);
                }
            }
        }
        __syncthreads();
        if (it + 2 < GNIT) fill(cur, 16 * (it + 2));
    }

#pragma unroll
    for (int i = 0; i < 4; i++) {
        int row = m0 + wr * 64 + i * 16 + g;
#pragma unroll
        for (int j = 0; j < 8; j++) {
            int col = n0 + wc * 64 + j * 8 + 2 * q;
            float* d = acc[i * 8 + j];
            *(float2*)&C[(size_t)row * N + col] = make_float2(d[0], d[1]);
            *(float2*)&C[(size_t)(row + 8) * N + col] = make_float2(d[2], d[3]);
        }
    }
}

__global__ __launch_bounds__(128) void gemm_pk(const unsigned* __restrict__ A,
                                               const unsigned* __restrict__ B,
                                               float* __restrict__ C) {
    gemm_pk_body(A, B, C, D_MODEL);
}

__global__ __launch_bounds__(128) void gemm_pk_qkv(
    const unsigned* __restrict__ A, const unsigned* __restrict__ Bq,
    const unsigned* __restrict__ Bk, const unsigned* __restrict__ Bv,
    float* __restrict__ Cq, float* __restrict__ Ck, float* __restrict__ Cv) {
    const unsigned* B = (blockIdx.z == 0) ? Bq : (blockIdx.z == 1) ? Bk : Bv;
    float* C = (blockIdx.z == 0) ? Cq : (blockIdx.z == 1) ? Ck : Cv;
    gemm_pk_body(A, B, C, D_MODEL);
}

// ---------------------------------------------------------------------------
// TF32 flash attention with packed operands + cp.async double-buffered K/V.
// 128 threads (4 warps), Bq=64, Bk=64, pitch-68 smem (proven layout).
// smem (u32): K0 [0,4352) K1 [4352,8704) V0 [8704,13056) V1 [13056,17408)
//             Ps [17408,21760)
// ---------------------------------------------------------------------------
__global__ __launch_bounds__(128) void attn_tc(const unsigned* __restrict__ Qp,
                                               const unsigned* __restrict__ Kp,
                                               const unsigned* __restrict__ Vtp,
                                               unsigned* __restrict__ Op) {
    extern __shared__ unsigned smem_u[];
    const unsigned smb = smem_u32p(smem_u);
    unsigned* Psu = smem_u + 17408;

    const int tid = threadIdx.x;
    const int lane = tid & 31;
    const int w = tid >> 5;
    const int g = lane >> 2;
    const int q = lane & 3;

    const int bh = blockIdx.y;
    const int b = bh >> 4;
    const int h = bh & 15;
    const int qt = (SEQ / 64 - 1) - blockIdx.x;  // heavy tiles first
    const int q0 = qt * 64;
    const int nkt = qt + 1;

    const unsigned* Kb = Kp + (size_t)bh * SEQ * 64;
    const unsigned* Qb = Qp + (size_t)bh * SEQ * 64;
    const unsigned* Vb = Vtp + (size_t)bh * 32 * 4096;

    auto fill = [&](int buf, int kt) {
        const unsigned* ksrc = Kb + (size_t)kt * 4096;
        const unsigned* vsrc = Vb + (size_t)kt * 4096;
#pragma unroll
        for (int it = 0; it < 8; it++) {
            int idx = tid + it * 128;   // 0..1023
            int r = idx >> 4;
            int c = idx & 15;
            cp16(smb + (buf * 4352 + r * 68 + 4 * c) * 4, ksrc + idx * 4);
        }
#pragma unroll
        for (int it = 0; it < 8; it++) {
            int idx = tid + it * 128;
            int r = idx >> 4;
            int c = idx & 15;
            cp16(smb + (8704 + buf * 4352 + r * 68 + 4 * c) * 4, vsrc + idx * 4);
        }
        CP_COMMIT();
    };

    fill(0, 0);
    if (nkt > 1) fill(1, 1);

    // Q tile: plain copy into Ps area (packed, scale pre-folded)
    {
        const uint4* qsrc = (const uint4*)(Qb + (size_t)q0 * 64);
#pragma unroll
        for (int it = 0; it < 8; it++) {
            int idx = tid + it * 128;
            int r = idx >> 4;
            int c = idx & 15;
            *(uint4*)&Psu[r * 68 + 4 * c] = qsrc[idx];
        }
    }
    __syncthreads();

    // Extract Q fragments (already tf32 bits, scaled)
    unsigned qf[8][4];
    {
        int r0 = (16 * w + g) * 68;
        int r1 = r0 + 8 * 68;
#pragma unroll
        for (int s = 0; s < 8; s++) {
            uint2 lo = *(const uint2*)&Psu[r0 + 8 * s + 2 * q];
            uint2 hi = *(const uint2*)&Psu[r1 + 8 * s + 2 * q];
            qf[s][0] = lo.x; qf[s][1] = hi.x; qf[s][2] = lo.y; qf[s][3] = hi.y;
        }
    }

    float oacc[8][4] = {};
    float m0 = -1e30f, m1 = -1e30f, l0 = 0.f, l1 = 0.f;

    const int pr0 = (16 * w + g) * 68;
    const int pr1 = pr0 + 8 * 68;
    const int pa = perm8(2 * q);
    const int pb = perm8(2 * q + 1);

    for (int kt = 0; kt < nkt; kt++) {
        const int cur = kt & 1;
        if (kt + 1 < nkt) { CP_WAIT(1); } else { CP_WAIT(0); }
        __syncthreads();

        const unsigned* Ksc = smem_u + cur * 4352;
        const unsigned* Vsc = smem_u + 8704 + cur * 4352;
        const int k0 = kt << 6;

        // S = Q K^T (warp: m16 x n64 x k64)
        float sacc[8][4];
#pragma unroll
        for (int j = 0; j < 8; j++)
#pragma unroll
            for (int r = 0; r < 4; r++) sacc[j][r] = 0.f;
#pragma unroll
        for (int j = 0; j < 8; j++) {
            int krow = (j * 8 + g) * 68;
#pragma unroll
            for (int s = 0; s < 8; s++) {
                uint2 bb = *(const uint2*)&Ksc[krow + 8 * s + 2 * q];
                MMA_TF32(sacc[j], qf[s], bb);
            }
        }

        // Causal mask (diagonal tile only)
        if (k0 + 63 > q0 + 16 * w) {
            int row0 = q0 + 16 * w + g;
            int row1 = row0 + 8;
#pragma unroll
            for (int j = 0; j < 8; j++) {
                int c0 = k0 + 8 * j + 2 * q;
                int c1 = c0 + 1;
                if (c0 > row0) sacc[j][0] = -1e30f;
                if (c1 > row0) sacc[j][1] = -1e30f;
                if (c0 > row1) sacc[j][2] = -1e30f;
                if (c1 > row1) sacc[j][3] = -1e30f;
            }
        }

        // Row max
        float mx0 = -1e30f, mx1 = -1e30f;
#pragma unroll
        for (int j = 0; j < 8; j++) {
            mx0 = fmaxf(mx0, fmaxf(sacc[j][0], sacc[j][1]));
            mx1 = fmaxf(mx1, fmaxf(sacc[j][2], sacc[j][3]));
        }
        mx0 = fmaxf(mx0, __shfl_xor_sync(0xffffffffu, mx0, 1));
        mx0 = fmaxf(mx0, __shfl_xor_sync(0xffffffffu, mx0, 2));
        mx1 = fmaxf(mx1, __shfl_xor_sync(0xffffffffu, mx1, 1));
        mx1 = fmaxf(mx1, __shfl_xor_sync(0xffffffffu, mx1, 2));

        float mn0 = fmaxf(m0, mx0);
        float mn1 = fmaxf(m1, mx1);
        float rs0 = exp2f((m0 - mn0) * LOG2EF);
        float rs1 = exp2f((m1 - mn1) * LOG2EF);
        m0 = mn0; m1 = mn1;

        float s0 = 0.f, s1 = 0.f;
#pragma unroll
        for (int j = 0; j < 8; j++) {
            float p0 = exp2f((sacc[j][0] - mn0) * LOG2EF);
            float p1 = exp2f((sacc[j][1] - mn0) * LOG2EF);
            float p2 = exp2f((sacc[j][2] - mn1) * LOG2EF);
            float p3 = exp2f((sacc[j][3] - mn1) * LOG2EF);
            s0 += p0 + p1;
            s1 += p2 + p3;
            Psu[pr0 + 8 * j + pa] = f2tf32(p0);
            Psu[pr0 + 8 * j + pb] = f2tf32(p1);
            Psu[pr1 + 8 * j + pa] = f2tf32(p2);
            Psu[pr1 + 8 * j + pb] = f2tf32(p3);
        }
        s0 += __shfl_xor_sync(0xffffffffu, s0, 1);
        s0 += __shfl_xor_sync(0xffffffffu, s0, 2);
        s1 += __shfl_xor_sync(0xffffffffu, s1, 1);
        s1 += __shfl_xor_sync(0xffffffffu, s1, 2);
        l0 = l0 * rs0 + s0;
        l1 = l1 * rs1 + s1;

#pragma unroll
        for (int j = 0; j < 8; j++) {
            oacc[j][0] *= rs0; oacc[j][1] *= rs0;
            oacc[j][2] *= rs1; oacc[j][3] *= rs1;
        }
        __syncwarp();  // Ps rows are per-warp

        // O += P V (warp: m16 x n64 x k64)
#pragma unroll
        for (int s = 0; s < 8; s++) {
            uint2 alo = *(const uint2*)&Psu[pr0 + 8 * s + 2 * q];
            uint2 ahi = *(const uint2*)&Psu[pr1 + 8 * s + 2 * q];
            unsigned af[4] = {alo.x, ahi.x, alo.y, ahi.y};
#pragma unroll
            for (int j = 0; j < 8; j++) {
                uint2 bb = *(const uint2*)&Vsc[(j * 8 + g) * 68 + 8 * s + 2 * q];
                MMA_TF32(oacc[j], af, bb);
            }
        }

        __syncthreads();   // all warps done reading cur buffers
        if (kt + 2 < nkt) fill(cur, kt + 2);
    }

    // Epilogue: write O packed tf32 (fragment order) for the final GEMM
    float inv0 = 1.f / l0;
    float inv1 = 1.f / l1;
    int s0r = q0 + 16 * w + g;
    unsigned* O0 = Op + (size_t)(b * SEQ + s0r) * D_MODEL + h * 64;
    unsigned* O1 = Op + (size_t)(b * SEQ + s0r + 8) * D_MODEL + h * 64;
#pragma unroll
    for (int j = 0; j < 8; j++) {
        O0[8 * j + pa] = f2tf32(oacc[j][0] * inv0);
        O0[8 * j + pb] = f2tf32(oacc[j][1] * inv0);
        O1[8 * j + pa] = f2tf32(oacc[j][2] * inv1);
        O1[8 * j + pb] = f2tf32(oacc[j][3] * inv1);
    }
}

// ---------------------------------------------------------------------------
extern "C" void kernel_launch(void* const* d_in, const int* in_sizes, int n_in,
                              void* d_out, int out_size) {
    const float* x  = (const float*)d_in[0];
    const int*   ps = (const int*)d_in[1];
    const float* Wq = (const float*)d_in[2];
    const float* Wk = (const float*)d_in[3];
    const float* Wv = (const float*)d_in[4];
    const float* Wo = (const float*)d_in[5];
    float* out = (float*)d_out;

    float *gq, *gk, *gv;
    unsigned *xp, *wqp, *wkp, *wvp, *wop, *qp, *kp, *vtp, *op;
    cudaGetSymbolAddress((void**)&gq, g_Q);
    cudaGetSymbolAddress((void**)&gk, g_K);
    cudaGetSymbolAddress((void**)&gv, g_V);
    cudaGetSymbolAddress((void**)&xp, g_Xp);
    cudaGetSymbolAddress((void**)&wqp, g_Wqp);
    cudaGetSymbolAddress((void**)&wkp, g_Wkp);
    cudaGetSymbolAddress((void**)&wvp, g_Wvp);
    cudaGetSymbolAddress((void**)&wop, g_Wop);
    cudaGetSymbolAddress((void**)&qp, g_Qp);
    cudaGetSymbolAddress((void**)&kp, g_Kp);
    cudaGetSymbolAddress((void**)&vtp, g_Vtp);
    cudaGetSymbolAddress((void**)&op, g_Op);

    const int gemm_smem = 12288 * 4;        // 49152 bytes
    const int attn_smem = 21760 * 4;        // 87040 bytes
    cudaFuncSetAttribute(gemm_pk, cudaFuncAttributeMaxDynamicSharedMemorySize,
                         gemm_smem);
    cudaFuncSetAttribute(gemm_pk_qkv,
                         cudaFuncAttributeMaxDynamicSharedMemorySize, gemm_smem);
    cudaFuncSetAttribute(attn_tc, cudaFuncAttributeMaxDynamicSharedMemorySize,
                         attn_smem);

    // Pack inputs (tf32 bits, fragment order)
    pack_rows<<<(MROWS * D_MODEL / 8 + 255) / 256, 256>>>(x, xp,
                                                          MROWS * D_MODEL / 8);
    pack_rows<<<(D_MODEL * D_MODEL / 8 + 255) / 256, 256>>>(
        Wq, wqp, D_MODEL * D_MODEL / 8);
    pack_rows<<<(D_MODEL * D_MODEL / 8 + 255) / 256, 256>>>(
        Wk, wkp, D_MODEL * D_MODEL / 8);
    pack_rows<<<(D_MODEL * D_MODEL / 8 + 255) / 256, 256>>>(
        Wv, wvp, D_MODEL * D_MODEL / 8);
    pack_rows<<<(D_MODEL * D_MODEL / 8 + 255) / 256, 256>>>(
        Wo, wop, D_MODEL * D_MODEL / 8);

    // Q/K/V projections (fp32 out)
    gemm_pk_qkv<<<dim3(8, 32, 3), 128, gemm_smem>>>(xp, wqp, wkp, wvp,
                                                    gq, gk, gv);

    // RoPE + pack Q/K; pack+transpose V
    rope_pack<<<(MROWS * 512) / 256, 256>>>(gq, gk, ps, qp, kp);
    pack_vt<<<dim3(32, 32), 256>>>(gv, vtp);

    // Attention (packed in, packed O out)
    attn_tc<<<dim3(SEQ / 64, BATCH * NUM_HEADS), 128, attn_smem>>>(qp, kp, vtp,
                                                                   op);

    // Output projection
    gemm_pk<<<dim3(8, 32), 128, gemm_smem>>>(op, wop, out);
}